// round 1
// baseline (speedup 1.0000x reference)
#include <cuda_runtime.h>
#include <math.h>

// Problem constants
constexpr int TM   = 64;    // rows (patches) per block
constexpr int KC   = 64;    // K-chunk
constexpr int NC   = 256;   // MLP width
constexpr int PNUM = 4096;  // patches per batch item
constexpr int ROWS = 8 * PNUM;  // 32768 rows per scale

// SMEM layout (floats):
//   sh : 64 x 257   (h tile, padded)       = 16448
//   sx : KC x 64    (gathered x chunk)     =  4096
//   sw : KC x 256   (weight chunk)         = 16384
constexpr int SH_STRIDE = 257;
constexpr int SMEM_FLOATS = 64 * SH_STRIDE + KC * TM + KC * NC;
constexpr int SMEM_BYTES  = SMEM_FLOATS * 4;

template <int C>
__global__ void __launch_bounds__(256, 1)
fused_scale_kernel(const float* __restrict__ feat,
                   const int*   __restrict__ pid,
                   const float* __restrict__ w1,
                   const float* __restrict__ b1,
                   const float* __restrict__ w2,
                   const float* __restrict__ b2,
                   float* __restrict__ out,
                   int HW)
{
    extern __shared__ float smem[];
    float* sh = smem;                               // h tile [64][257]
    float* sx = smem + 64 * SH_STRIDE;              // x chunk [KC][64]
    float* sw = smem + 64 * SH_STRIDE + KC * TM;    // w chunk [KC][256]
    __shared__ int spid[TM];

    const int tid = threadIdx.x;
    const int ty  = tid >> 4;   // 0..15 : row group (4 rows each)
    const int tx  = tid & 15;   // 0..15 : col group (cols tx*4 + 64j + jj)

    const int row0 = blockIdx.x * TM;
    const int b    = row0 / PNUM;          // whole block shares one batch item
    const int p0   = row0 - b * PNUM;

    if (tid < TM) spid[tid] = pid[b * PNUM + p0 + tid];

    // bias registers for this thread's 16 columns
    float bias1[16], bias2[16];
#pragma unroll
    for (int j = 0; j < 4; j++)
#pragma unroll
        for (int jj = 0; jj < 4; jj++) {
            int col = tx * 4 + 64 * j + jj;
            bias1[j * 4 + jj] = __ldg(&b1[col]);
            bias2[j * 4 + jj] = __ldg(&b2[col]);
        }

    const float* featb = feat + (size_t)b * C * HW;

    float acc[4][16];
#pragma unroll
    for (int i = 0; i < 4; i++)
#pragma unroll
        for (int j = 0; j < 16; j++) acc[i][j] = 0.f;

    __syncthreads();  // spid visible

    // ---------------- GEMM1: h = relu(x @ w1 + b1) ----------------
    for (int k0 = 0; k0 < C; k0 += KC) {
        // gather x chunk into sx[k][r]  (scattered 4B global loads)
#pragma unroll
        for (int t = tid; t < KC * TM; t += 256) {
            int k = t >> 6;
            int r = t & 63;
            sx[t] = __ldg(&featb[(size_t)(k0 + k) * HW + spid[r]]);
        }
        // stream w1 chunk (contiguous, float4)
        {
            const float4* wsrc = (const float4*)(w1 + (size_t)k0 * NC);
            float4* wdst = (float4*)sw;
#pragma unroll
            for (int t = tid; t < KC * NC / 4; t += 256) wdst[t] = __ldg(&wsrc[t]);
        }
        __syncthreads();

#pragma unroll 4
        for (int k = 0; k < KC; k++) {
            float4 a4 = *(const float4*)&sx[k * TM + ty * 4];
            float a[4] = {a4.x, a4.y, a4.z, a4.w};
#pragma unroll
            for (int j = 0; j < 4; j++) {
                float4 b4 = *(const float4*)&sw[k * NC + tx * 4 + 64 * j];
#pragma unroll
                for (int i = 0; i < 4; i++) {
                    acc[i][j * 4 + 0] = fmaf(a[i], b4.x, acc[i][j * 4 + 0]);
                    acc[i][j * 4 + 1] = fmaf(a[i], b4.y, acc[i][j * 4 + 1]);
                    acc[i][j * 4 + 2] = fmaf(a[i], b4.z, acc[i][j * 4 + 2]);
                    acc[i][j * 4 + 3] = fmaf(a[i], b4.w, acc[i][j * 4 + 3]);
                }
            }
        }
        __syncthreads();
    }

    // relu + bias, write h to sh[row][col] (padded), reset acc
#pragma unroll
    for (int i = 0; i < 4; i++) {
        int r = ty * 4 + i;
#pragma unroll
        for (int j = 0; j < 16; j++) {
            int col = tx * 4 + 64 * (j >> 2) + (j & 3);
            float v = acc[i][j] + bias1[j];
            sh[r * SH_STRIDE + col] = fmaxf(v, 0.f);
            acc[i][j] = 0.f;
        }
    }
    __syncthreads();

    // ---------------- GEMM2: y = h @ w2 + b2 ----------------
    for (int k0 = 0; k0 < NC; k0 += KC) {
        {
            const float4* wsrc = (const float4*)(w2 + (size_t)k0 * NC);
            float4* wdst = (float4*)sw;
#pragma unroll
            for (int t = tid; t < KC * NC / 4; t += 256) wdst[t] = __ldg(&wsrc[t]);
        }
        __syncthreads();

#pragma unroll 4
        for (int k = 0; k < KC; k++) {
            int kk = k0 + k;
            float a[4];
#pragma unroll
            for (int i = 0; i < 4; i++) a[i] = sh[(ty * 4 + i) * SH_STRIDE + kk];
#pragma unroll
            for (int j = 0; j < 4; j++) {
                float4 b4 = *(const float4*)&sw[k * NC + tx * 4 + 64 * j];
#pragma unroll
                for (int i = 0; i < 4; i++) {
                    acc[i][j * 4 + 0] = fmaf(a[i], b4.x, acc[i][j * 4 + 0]);
                    acc[i][j * 4 + 1] = fmaf(a[i], b4.y, acc[i][j * 4 + 1]);
                    acc[i][j * 4 + 2] = fmaf(a[i], b4.z, acc[i][j * 4 + 2]);
                    acc[i][j * 4 + 3] = fmaf(a[i], b4.w, acc[i][j * 4 + 3]);
                }
            }
        }
        __syncthreads();
    }

    // ---------------- bias2 + L2 normalize + store ----------------
#pragma unroll
    for (int i = 0; i < 4; i++) {
        float ss = 0.f;
#pragma unroll
        for (int j = 0; j < 16; j++) {
            float v = acc[i][j] + bias2[j];
            acc[i][j] = v;
            ss = fmaf(v, v, ss);
        }
        // reduce across the 16 tx-lanes sharing this row (contiguous half-warp)
#pragma unroll
        for (int off = 8; off >= 1; off >>= 1)
            ss += __shfl_xor_sync(0xffffffffu, ss, off, 16);
        float inv = 1.f / (sqrtf(ss) + 1e-7f);

        size_t orow = (size_t)(row0 + ty * 4 + i) * NC;
#pragma unroll
        for (int j = 0; j < 4; j++) {
            float4 o;
            o.x = acc[i][j * 4 + 0] * inv;
            o.y = acc[i][j * 4 + 1] * inv;
            o.z = acc[i][j * 4 + 2] * inv;
            o.w = acc[i][j * 4 + 3] * inv;
            *(float4*)&out[orow + tx * 4 + 64 * j] = o;
        }
    }
}

extern "C" void kernel_launch(void* const* d_in, const int* in_sizes, int n_in,
                              void* d_out, int out_size)
{
    // Two possible metadata orderings:
    //  signature order: feat0,feat1,feat2,pid0..2, (w1,b1,w2,b2) x3, num_patches
    //  dict order:      (feat,pid,w1,b1,w2,b2) per scale, num_patches
    // Disambiguate via in_sizes[1]: feat1 = 16777216 elems vs pid0 = 32768.
    const bool sig_order = (n_in > 1) && (in_sizes[1] == 16777216);

    const float* feat[3];
    const int*   pid[3];
    const float *w1[3], *b1[3], *w2[3], *b2[3];

    if (sig_order) {
        for (int s = 0; s < 3; s++) {
            feat[s] = (const float*)d_in[s];
            pid[s]  = (const int*)  d_in[3 + s];
            w1[s]   = (const float*)d_in[6 + 4 * s];
            b1[s]   = (const float*)d_in[7 + 4 * s];
            w2[s]   = (const float*)d_in[8 + 4 * s];
            b2[s]   = (const float*)d_in[9 + 4 * s];
        }
    } else {
        for (int s = 0; s < 3; s++) {
            feat[s] = (const float*)d_in[6 * s + 0];
            pid[s]  = (const int*)  d_in[6 * s + 1];
            w1[s]   = (const float*)d_in[6 * s + 2];
            b1[s]   = (const float*)d_in[6 * s + 3];
            w2[s]   = (const float*)d_in[6 * s + 4];
            b2[s]   = (const float*)d_in[6 * s + 5];
        }
    }

    float* out = (float*)d_out;

    // Opt into >48KB dynamic smem (idempotent; not a stream op, capture-safe)
    cudaFuncSetAttribute(fused_scale_kernel<128>,
                         cudaFuncAttributeMaxDynamicSharedMemorySize, SMEM_BYTES);
    cudaFuncSetAttribute(fused_scale_kernel<256>,
                         cudaFuncAttributeMaxDynamicSharedMemorySize, SMEM_BYTES);
    cudaFuncSetAttribute(fused_scale_kernel<512>,
                         cudaFuncAttributeMaxDynamicSharedMemorySize, SMEM_BYTES);

    dim3 grid(ROWS / TM);   // 512
    dim3 block(256);

    fused_scale_kernel<128><<<grid, block, SMEM_BYTES>>>(
        feat[0], pid[0], w1[0], b1[0], w2[0], b2[0],
        out, 256 * 128);
    fused_scale_kernel<256><<<grid, block, SMEM_BYTES>>>(
        feat[1], pid[1], w1[1], b1[1], w2[1], b2[1],
        out + (size_t)ROWS * NC, 128 * 64);
    fused_scale_kernel<512><<<grid, block, SMEM_BYTES>>>(
        feat[2], pid[2], w1[2], b1[2], w2[2], b2[2],
        out + (size_t)2 * ROWS * NC, 64 * 32);
}

// round 3
// speedup vs baseline: 1.3737x; 1.3737x over previous
#include <cuda_runtime.h>
#include <math.h>

// Problem constants
constexpr int TM   = 64;    // rows (patches) per block
constexpr int KC   = 32;    // K-chunk
constexpr int NC   = 256;   // MLP width
constexpr int PNUM = 4096;  // patches per batch item
constexpr int ROWS = 8 * PNUM;  // 32768 rows per scale

// SMEM layout (floats):
//   sh_t : 256 x 68  (h tile TRANSPOSED [k][row], stride mult-of-4 for float4 align)
//   sx   : KC x 64   (gathered x chunk, [k][row])
//   sw   : KC x 256  (weight chunk, [k][n])
constexpr int SHT_STRIDE  = 68;               // 16B-aligned rows; (col+ty)%8 spreads banks
constexpr int SHT_FLOATS  = NC * SHT_STRIDE;  // 17408
constexpr int SX_FLOATS   = KC * TM;          // 2048
constexpr int SW_FLOATS   = KC * NC;          // 8192
constexpr int SMEM_BYTES  = (SHT_FLOATS + SX_FLOATS + SW_FLOATS) * 4;  // 110,592 B

struct Params {
    const float* feat[3];
    const int*   pid[3];
    const float* w1[3];
    const float* b1[3];
    const float* w2[3];
    const float* b2[3];
    float*       out;
};

__global__ void __launch_bounds__(256, 2)
fused_all_kernel(Params P)
{
    extern __shared__ float smem[];
    float* sh = smem;                         // h^T tile [256][68]
    float* sx = smem + SHT_FLOATS;            // x chunk  [KC][64]
    float* sw = sx + SX_FLOATS;               // w chunk  [KC][256]
    __shared__ int spid[TM];

    const int s  = blockIdx.x % 3;            // scale id (interleaved for balance)
    const int bi = blockIdx.x / 3;            // tile index within scale
    const int C  = 128 << s;                  // 128, 256, 512
    const int HW = 32768 >> (2 * s);          // 32768, 8192, 2048

    const float* __restrict__ feat = P.feat[s];
    const int*   __restrict__ pid  = P.pid[s];
    const float* __restrict__ w1   = P.w1[s];
    const float* __restrict__ b1   = P.b1[s];
    const float* __restrict__ w2   = P.w2[s];
    const float* __restrict__ b2   = P.b2[s];
    float* __restrict__ out        = P.out + (size_t)s * ROWS * NC;

    const int tid = threadIdx.x;
    const int ty  = tid >> 4;   // 0..15 : row group (4 rows each)
    const int tx  = tid & 15;   // 0..15 : col group

    const int row0 = bi * TM;
    const int b    = row0 / PNUM;             // whole block shares one batch item
    const int p0   = row0 - b * PNUM;

    if (tid < TM) spid[tid] = pid[b * PNUM + p0 + tid];

    const float* featb = feat + (size_t)b * C * HW;

    // acc initialized with bias1 (saves 32 bias registers + the adds)
    float acc[4][16];
#pragma unroll
    for (int j = 0; j < 4; j++)
#pragma unroll
        for (int jj = 0; jj < 4; jj++) {
            float bv = __ldg(&b1[tx * 4 + 64 * j + jj]);
#pragma unroll
            for (int i = 0; i < 4; i++) acc[i][j * 4 + jj] = bv;
        }

    __syncthreads();  // spid visible

    // ---------------- GEMM1: h = relu(x @ w1 + b1) ----------------
    for (int k0 = 0; k0 < C; k0 += KC) {
        // gather x chunk into sx[k][r]  (scattered 4B global loads)
#pragma unroll
        for (int t = tid; t < KC * TM; t += 256) {
            int k = t >> 6;
            int r = t & 63;
            sx[t] = __ldg(&featb[(size_t)(k0 + k) * HW + spid[r]]);
        }
        // stream w1 chunk (contiguous, float4)
        {
            const float4* wsrc = (const float4*)(w1 + (size_t)k0 * NC);
            float4* wdst = (float4*)sw;
#pragma unroll
            for (int t = tid; t < KC * NC / 4; t += 256) wdst[t] = __ldg(&wsrc[t]);
        }
        __syncthreads();

#pragma unroll 8
        for (int k = 0; k < KC; k++) {
            float4 a4 = *(const float4*)&sx[k * TM + ty * 4];
            float a[4] = {a4.x, a4.y, a4.z, a4.w};
#pragma unroll
            for (int j = 0; j < 4; j++) {
                float4 b4 = *(const float4*)&sw[k * NC + tx * 4 + 64 * j];
#pragma unroll
                for (int i = 0; i < 4; i++) {
                    acc[i][j * 4 + 0] = fmaf(a[i], b4.x, acc[i][j * 4 + 0]);
                    acc[i][j * 4 + 1] = fmaf(a[i], b4.y, acc[i][j * 4 + 1]);
                    acc[i][j * 4 + 2] = fmaf(a[i], b4.z, acc[i][j * 4 + 2]);
                    acc[i][j * 4 + 3] = fmaf(a[i], b4.w, acc[i][j * 4 + 3]);
                }
            }
        }
        __syncthreads();
    }

    // relu, write h TRANSPOSED: sh[col][row], rows ty*4..+3 contiguous -> STS.128
#pragma unroll
    for (int j = 0; j < 16; j++) {
        int col = tx * 4 + 64 * (j >> 2) + (j & 3);
        float4 v;
        v.x = fmaxf(acc[0][j], 0.f);
        v.y = fmaxf(acc[1][j], 0.f);
        v.z = fmaxf(acc[2][j], 0.f);
        v.w = fmaxf(acc[3][j], 0.f);
        *(float4*)&sh[col * SHT_STRIDE + ty * 4] = v;
    }

    // re-init acc with bias2
#pragma unroll
    for (int j = 0; j < 4; j++)
#pragma unroll
        for (int jj = 0; jj < 4; jj++) {
            float bv = __ldg(&b2[tx * 4 + 64 * j + jj]);
#pragma unroll
            for (int i = 0; i < 4; i++) acc[i][j * 4 + jj] = bv;
        }
    __syncthreads();

    // ---------------- GEMM2: y = h @ w2 + b2 ----------------
    for (int k0 = 0; k0 < NC; k0 += KC) {
        {
            const float4* wsrc = (const float4*)(w2 + (size_t)k0 * NC);
            float4* wdst = (float4*)sw;
#pragma unroll
            for (int t = tid; t < KC * NC / 4; t += 256) wdst[t] = __ldg(&wsrc[t]);
        }
        __syncthreads();

#pragma unroll 8
        for (int k = 0; k < KC; k++) {
            int kk = k0 + k;
            float4 a4 = *(const float4*)&sh[kk * SHT_STRIDE + ty * 4];  // broadcast LDS.128
            float a[4] = {a4.x, a4.y, a4.z, a4.w};
#pragma unroll
            for (int j = 0; j < 4; j++) {
                float4 b4 = *(const float4*)&sw[k * NC + tx * 4 + 64 * j];
#pragma unroll
                for (int i = 0; i < 4; i++) {
                    acc[i][j * 4 + 0] = fmaf(a[i], b4.x, acc[i][j * 4 + 0]);
                    acc[i][j * 4 + 1] = fmaf(a[i], b4.y, acc[i][j * 4 + 1]);
                    acc[i][j * 4 + 2] = fmaf(a[i], b4.z, acc[i][j * 4 + 2]);
                    acc[i][j * 4 + 3] = fmaf(a[i], b4.w, acc[i][j * 4 + 3]);
                }
            }
        }
        __syncthreads();
    }

    // ---------------- L2 normalize + store ----------------
#pragma unroll
    for (int i = 0; i < 4; i++) {
        float ss = 0.f;
#pragma unroll
        for (int j = 0; j < 16; j++) ss = fmaf(acc[i][j], acc[i][j], ss);
        // reduce across the 16 tx-lanes sharing this row (contiguous half-warp)
#pragma unroll
        for (int off = 8; off >= 1; off >>= 1)
            ss += __shfl_xor_sync(0xffffffffu, ss, off, 16);
        float inv = 1.f / (sqrtf(ss) + 1e-7f);

        size_t orow = (size_t)(row0 + ty * 4 + i) * NC;
#pragma unroll
        for (int j = 0; j < 4; j++) {
            float4 o;
            o.x = acc[i][j * 4 + 0] * inv;
            o.y = acc[i][j * 4 + 1] * inv;
            o.z = acc[i][j * 4 + 2] * inv;
            o.w = acc[i][j * 4 + 3] * inv;
            *(float4*)&out[orow + tx * 4 + 64 * j] = o;
        }
    }
}

extern "C" void kernel_launch(void* const* d_in, const int* in_sizes, int n_in,
                              void* d_out, int out_size)
{
    // Two possible metadata orderings; disambiguate via in_sizes[1]:
    // feat1 = 16777216 elems (signature order) vs pid0 = 32768 (dict order).
    const bool sig_order = (n_in > 1) && (in_sizes[1] == 16777216);

    Params P;
    if (sig_order) {
        for (int s = 0; s < 3; s++) {
            P.feat[s] = (const float*)d_in[s];
            P.pid[s]  = (const int*)  d_in[3 + s];
            P.w1[s]   = (const float*)d_in[6 + 4 * s];
            P.b1[s]   = (const float*)d_in[7 + 4 * s];
            P.w2[s]   = (const float*)d_in[8 + 4 * s];
            P.b2[s]   = (const float*)d_in[9 + 4 * s];
        }
    } else {
        for (int s = 0; s < 3; s++) {
            P.feat[s] = (const float*)d_in[6 * s + 0];
            P.pid[s]  = (const int*)  d_in[6 * s + 1];
            P.w1[s]   = (const float*)d_in[6 * s + 2];
            P.b1[s]   = (const float*)d_in[6 * s + 3];
            P.w2[s]   = (const float*)d_in[6 * s + 4];
            P.b2[s]   = (const float*)d_in[6 * s + 5];
        }
    }
    P.out = (float*)d_out;

    cudaFuncSetAttribute(fused_all_kernel,
                         cudaFuncAttributeMaxDynamicSharedMemorySize, SMEM_BYTES);

    dim3 grid(3 * (ROWS / TM));   // 1536 blocks, scales interleaved
    dim3 block(256);
    fused_all_kernel<<<grid, block, SMEM_BYTES>>>(P);
}

// round 6
// speedup vs baseline: 2.0629x; 1.5017x over previous
#include <cuda_runtime.h>
#include <cuda_bf16.h>
#include <math.h>
#include <stdint.h>

// ---------------- problem constants ----------------
constexpr int NCOL = 256;     // MLP width
constexpr int PNUM = 4096;    // patches per batch item
constexpr int ROWS = 32768;   // rows per scale
constexpr int TM   = 64;      // M rows per CTA
constexpr int KT   = 32;      // K tile

// weight scratch offsets (bf16 elements): [w1_0, w2_0, w1_1, w2_1, w1_2, w2_2]
__host__ __device__ constexpr int W1OFF(int s) {
    return s == 0 ? 0 : (s == 1 ? 98304 : 229376);
}
__host__ __device__ constexpr int W2OFF(int s) {
    return s == 0 ? 32768 : (s == 1 ? 163840 : 360448);
}
constexpr int WTOTAL = 425984;

__device__ uint4 g_whi4[WTOTAL / 8];   // transposed [n][k] bf16 hi, 32-k tiles
__device__ uint4 g_wlo4[WTOTAL / 8];   // lo residuals

// ---------------- smem word offsets ----------------
// sxh/sxl : A tile   64 rows x 20 words (stride 80B, conflict-free)
// swh/swl : W tile  256 rows x 20 words
// shh/shl : h tile   64 rows x 132 words (stride 528B)
constexpr int O_SXH = 0;
constexpr int O_SXL = 1280;
constexpr int O_SWH = 2560;
constexpr int O_SWL = 7680;
constexpr int O_SHH = 12800;
constexpr int O_SHL = 21248;
constexpr int O_SB1 = 29696;
constexpr int O_SB2 = 29952;
constexpr int O_SSP = 30208;   // 128 floats: per-row partial sumsq [row][wn]
constexpr int O_PID = 30336;   // 64 ints
constexpr int SMEM_WORDS = 30400;
constexpr int SMEM_BYTES = SMEM_WORDS * 4;   // 121,600 B

struct Params {
    const float* feat[3];
    const int*   pid[3];
    const float* w1[3];
    const float* b1[3];
    const float* w2[3];
    const float* b2[3];
    float*       out;
};

__device__ __forceinline__ uint32_t pack_bf2(__nv_bfloat16 lo, __nv_bfloat16 hi) {
    return (uint32_t)__bfloat16_as_ushort(hi) << 16 | (uint32_t)__bfloat16_as_ushort(lo);
}
__device__ __forceinline__ void split2(float v0, float v1, uint32_t& hw, uint32_t& lw) {
    __nv_bfloat16 h0 = __float2bfloat16(v0);
    __nv_bfloat16 h1 = __float2bfloat16(v1);
    __nv_bfloat16 l0 = __float2bfloat16(v0 - __bfloat162float(h0));
    __nv_bfloat16 l1 = __float2bfloat16(v1 - __bfloat162float(h1));
    hw = pack_bf2(h0, h1);
    lw = pack_bf2(l0, l1);
}
__device__ __forceinline__ void mma16816(float* d, const uint32_t* a,
                                         uint32_t b0, uint32_t b1) {
    asm volatile(
        "mma.sync.aligned.m16n8k16.row.col.f32.bf16.bf16.f32 "
        "{%0,%1,%2,%3}, {%4,%5,%6,%7}, {%8,%9}, {%0,%1,%2,%3};"
        : "+f"(d[0]), "+f"(d[1]), "+f"(d[2]), "+f"(d[3])
        : "r"(a[0]), "r"(a[1]), "r"(a[2]), "r"(a[3]), "r"(b0), "r"(b1));
}

// ---------------- weight prep: fp32 [k][n] -> bf16 hi/lo transposed [n][k] tiles ----
__global__ void prep_weights(Params P)
{
    __nv_bfloat16* ghi = (__nv_bfloat16*)g_whi4;
    __nv_bfloat16* glo = (__nv_bfloat16*)g_wlo4;
    for (int m = 0; m < 6; m++) {
        int s = m >> 1;
        bool isw2 = m & 1;
        const float* w = isw2 ? P.w2[s] : P.w1[s];
        int K   = isw2 ? 256 : (128 << s);
        int off = isw2 ? W2OFF(s) : W1OFF(s);
        int nel = K * 256;
        for (int e = blockIdx.x * blockDim.x + threadIdx.x; e < nel;
             e += gridDim.x * blockDim.x) {
            int k = e >> 8, n = e & 255;
            float v = w[e];
            __nv_bfloat16 hi = __float2bfloat16(v);
            __nv_bfloat16 lo = __float2bfloat16(v - __bfloat162float(hi));
            // tile (k/32): element (n, k%32) at n*32 + k%32; tiles 8192 elems
            int d = off + (k >> 5) * 8192 + n * 32 + (k & 31);
            ghi[d] = hi;
            glo[d] = lo;
        }
    }
}

// ---------------- fused kernel ----------------
__global__ void __launch_bounds__(256, 1)
fused_mma(Params P)
{
    extern __shared__ uint32_t smw[];
    uint32_t* sxh = smw + O_SXH;
    uint32_t* sxl = smw + O_SXL;
    uint32_t* swh = smw + O_SWH;
    uint32_t* swl = smw + O_SWL;
    uint32_t* shh = smw + O_SHH;
    uint32_t* shl = smw + O_SHL;
    float*    sb1 = (float*)(smw + O_SB1);
    float*    sb2 = (float*)(smw + O_SB2);
    float*    ssp = (float*)(smw + O_SSP);
    int*      spid = (int*)(smw + O_PID);

    const int tid  = threadIdx.x;
    const int wid  = tid >> 5;
    const int lane = tid & 31;
    const int wm   = wid & 3;          // M group: rows wm*16..+15
    const int wn   = wid >> 2;         // N half: cols wn*128..+127
    const int gr   = lane >> 2;        // 0..7
    const int c    = lane & 3;         // 0..3
    const int rowA = wm * 16 + gr;

    const int s  = blockIdx.x % 3;
    const int bi = blockIdx.x / 3;
    const int C  = 128 << s;
    const int HW = 32768 >> (2 * s);

    const float* __restrict__ feat = P.feat[s];
    const int*   __restrict__ pid  = P.pid[s];

    const int row0 = bi * TM;
    const int b    = row0 >> 12;
    const int p0   = row0 & (PNUM - 1);

    if (tid < TM) spid[tid] = pid[b * PNUM + p0 + tid];
    sb1[tid] = __ldg(&P.b1[s][tid]);
    sb2[tid] = __ldg(&P.b2[s][tid]);
    __syncthreads();

    const float* featb = feat + (size_t)b * C * HW;
    const __nv_bfloat16* ghi = (const __nv_bfloat16*)g_whi4;
    const __nv_bfloat16* glo = (const __nv_bfloat16*)g_wlo4;

    float acc[16][4];
#pragma unroll
    for (int nt = 0; nt < 16; nt++)
#pragma unroll
        for (int q = 0; q < 4; q++) acc[nt][q] = 0.f;

    // ================= GEMM1: h = relu(x @ w1 + b1) =================
    const int NT1 = C / KT;
    for (int t = 0; t < NT1; t++) {
        const int k0 = t * KT;
        // fill W tile (coalesced uint4 from pre-transposed scratch)
        {
            const uint4* srch = (const uint4*)(ghi + W1OFF(s) + t * 8192);
            const uint4* srcl = (const uint4*)(glo + W1OFF(s) + t * 8192);
#pragma unroll
            for (int i = 0; i < 4; i++) {
                int u = tid + i * 256;
                int n = u >> 2, q = u & 3;
                *(uint4*)((char*)swh + n * 80 + q * 16) = __ldg(&srch[u]);
                *(uint4*)((char*)swl + n * 80 + q * 16) = __ldg(&srcl[u]);
            }
        }
        // fill A tile (gather + split)
#pragma unroll
        for (int i = 0; i < 4; i++) {
            int wv = tid + i * 256;          // word index: 64 rows x 16 k-pairs
            int r  = wv & 63;
            int kp = wv >> 6;                // 0..15
            int k  = k0 + kp * 2;
            int pidr = spid[r];
            float v0 = __ldg(&featb[(size_t)k * HW + pidr]);
            float v1 = __ldg(&featb[(size_t)(k + 1) * HW + pidr]);
            uint32_t hw, lw;
            split2(v0, v1, hw, lw);
            sxh[r * 20 + kp] = hw;
            sxl[r * 20 + kp] = lw;
        }
        __syncthreads();

#pragma unroll
        for (int ks = 0; ks < 2; ks++) {
            uint32_t ah[4], al[4];
            const int ab = rowA * 20 + ks * 8 + c;
            ah[0] = sxh[ab];       ah[1] = sxh[ab + 160];
            ah[2] = sxh[ab + 4];   ah[3] = sxh[ab + 164];
            al[0] = sxl[ab];       al[1] = sxl[ab + 160];
            al[2] = sxl[ab + 4];   al[3] = sxl[ab + 164];
#pragma unroll
            for (int nt = 0; nt < 16; nt++) {
                const int bb = (wn * 128 + nt * 8 + gr) * 20 + ks * 8 + c;
                uint32_t bh0 = swh[bb], bh1 = swh[bb + 4];
                uint32_t bl0 = swl[bb], bl1 = swl[bb + 4];
                mma16816(acc[nt], ah, bh0, bh1);
                mma16816(acc[nt], ah, bl0, bl1);
                mma16816(acc[nt], al, bh0, bh1);
            }
        }
        __syncthreads();
    }

    // ---- h epilogue: +b1, relu, split, write to h smem; reset acc ----
#pragma unroll
    for (int nt = 0; nt < 16; nt++) {
        const int n  = wn * 128 + nt * 8 + 2 * c;
        const int wi = wn * 64 + nt * 4 + c;
        float v0 = fmaxf(acc[nt][0] + sb1[n],     0.f);
        float v1 = fmaxf(acc[nt][1] + sb1[n + 1], 0.f);
        float v2 = fmaxf(acc[nt][2] + sb1[n],     0.f);
        float v3 = fmaxf(acc[nt][3] + sb1[n + 1], 0.f);
        uint32_t hw, lw;
        split2(v0, v1, hw, lw);
        shh[rowA * 132 + wi] = hw;
        shl[rowA * 132 + wi] = lw;
        split2(v2, v3, hw, lw);
        shh[(rowA + 8) * 132 + wi] = hw;
        shl[(rowA + 8) * 132 + wi] = lw;
#pragma unroll
        for (int q = 0; q < 4; q++) acc[nt][q] = 0.f;
    }

    // ================= GEMM2: y = h @ w2 + b2 =================
    for (int t = 0; t < 8; t++) {
        {
            const uint4* srch = (const uint4*)(ghi + W2OFF(s) + t * 8192);
            const uint4* srcl = (const uint4*)(glo + W2OFF(s) + t * 8192);
#pragma unroll
            for (int i = 0; i < 4; i++) {
                int u = tid + i * 256;
                int n = u >> 2, q = u & 3;
                *(uint4*)((char*)swh + n * 80 + q * 16) = __ldg(&srch[u]);
                *(uint4*)((char*)swl + n * 80 + q * 16) = __ldg(&srcl[u]);
            }
        }
        __syncthreads();   // W visible; also (t==0) h visible to all

#pragma unroll
        for (int ks = 0; ks < 2; ks++) {
            uint32_t ah[4], al[4];
            const int ab = rowA * 132 + t * 16 + ks * 8 + c;
            ah[0] = shh[ab];        ah[1] = shh[ab + 1056];
            ah[2] = shh[ab + 4];    ah[3] = shh[ab + 1060];
            al[0] = shl[ab];        al[1] = shl[ab + 1056];
            al[2] = shl[ab + 4];    al[3] = shl[ab + 1060];
#pragma unroll
            for (int nt = 0; nt < 16; nt++) {
                const int bb = (wn * 128 + nt * 8 + gr) * 20 + ks * 8 + c;
                uint32_t bh0 = swh[bb], bh1 = swh[bb + 4];
                uint32_t bl0 = swl[bb], bl1 = swl[bb + 4];
                mma16816(acc[nt], ah, bh0, bh1);
                mma16816(acc[nt], ah, bl0, bl1);
                mma16816(acc[nt], al, bh0, bh1);
            }
        }
        __syncthreads();
    }

    // ================= epilogue: +b2, L2 normalize, store =================
    float ss0 = 0.f, ss1 = 0.f;
#pragma unroll
    for (int nt = 0; nt < 16; nt++) {
        const int n = wn * 128 + nt * 8 + 2 * c;
        acc[nt][0] += sb2[n];
        acc[nt][1] += sb2[n + 1];
        acc[nt][2] += sb2[n];
        acc[nt][3] += sb2[n + 1];
        ss0 = fmaf(acc[nt][0], acc[nt][0], fmaf(acc[nt][1], acc[nt][1], ss0));
        ss1 = fmaf(acc[nt][2], acc[nt][2], fmaf(acc[nt][3], acc[nt][3], ss1));
    }
    // reduce over the 4 c-lanes of this row-group (xor 1,2 stays in the quad)
    ss0 += __shfl_xor_sync(0xffffffffu, ss0, 1);
    ss0 += __shfl_xor_sync(0xffffffffu, ss0, 2);
    ss1 += __shfl_xor_sync(0xffffffffu, ss1, 1);
    ss1 += __shfl_xor_sync(0xffffffffu, ss1, 2);
    if (c == 0) {
        ssp[rowA * 2 + wn]       = ss0;
        ssp[(rowA + 8) * 2 + wn] = ss1;
    }
    __syncthreads();
    const float inv0 = 1.f / (sqrtf(ssp[rowA * 2] + ssp[rowA * 2 + 1]) + 1e-7f);
    const float inv1 = 1.f / (sqrtf(ssp[(rowA + 8) * 2] + ssp[(rowA + 8) * 2 + 1]) + 1e-7f);

    float* __restrict__ out = P.out + ((size_t)s * ROWS + row0) * NCOL;
#pragma unroll
    for (int nt = 0; nt < 16; nt++) {
        const int n = wn * 128 + nt * 8 + 2 * c;
        float2 o0 = make_float2(acc[nt][0] * inv0, acc[nt][1] * inv0);
        float2 o1 = make_float2(acc[nt][2] * inv1, acc[nt][3] * inv1);
        *(float2*)&out[(size_t)rowA * NCOL + n]       = o0;
        *(float2*)&out[(size_t)(rowA + 8) * NCOL + n] = o1;
    }
}

// ---------------- launch ----------------
extern "C" void kernel_launch(void* const* d_in, const int* in_sizes, int n_in,
                              void* d_out, int out_size)
{
    const bool sig_order = (n_in > 1) && (in_sizes[1] == 16777216);

    Params P;
    if (sig_order) {
        for (int s = 0; s < 3; s++) {
            P.feat[s] = (const float*)d_in[s];
            P.pid[s]  = (const int*)  d_in[3 + s];
            P.w1[s]   = (const float*)d_in[6 + 4 * s];
            P.b1[s]   = (const float*)d_in[7 + 4 * s];
            P.w2[s]   = (const float*)d_in[8 + 4 * s];
            P.b2[s]   = (const float*)d_in[9 + 4 * s];
        }
    } else {
        for (int s = 0; s < 3; s++) {
            P.feat[s] = (const float*)d_in[6 * s + 0];
            P.pid[s]  = (const int*)  d_in[6 * s + 1];
            P.w1[s]   = (const float*)d_in[6 * s + 2];
            P.b1[s]   = (const float*)d_in[6 * s + 3];
            P.w2[s]   = (const float*)d_in[6 * s + 4];
            P.b2[s]   = (const float*)d_in[6 * s + 5];
        }
    }
    P.out = (float*)d_out;

    cudaFuncSetAttribute(fused_mma, cudaFuncAttributeMaxDynamicSharedMemorySize,
                         SMEM_BYTES);

    prep_weights<<<256, 256>>>(P);
    fused_mma<<<3 * (ROWS / TM), 256, SMEM_BYTES>>>(P);
}

// round 7
// speedup vs baseline: 2.5279x; 1.2254x over previous
#include <cuda_runtime.h>
#include <cuda_bf16.h>
#include <math.h>
#include <stdint.h>

// ---------------- problem constants ----------------
constexpr int NCOL = 256;
constexpr int PNUM = 4096;
constexpr int ROWS = 32768;
constexpr int TM   = 64;      // M rows per CTA
constexpr int KT   = 32;      // K tile

__host__ __device__ constexpr int W1OFF(int s) {
    return s == 0 ? 0 : (s == 1 ? 98304 : 229376);
}
__host__ __device__ constexpr int W2OFF(int s) {
    return s == 0 ? 32768 : (s == 1 ? 163840 : 360448);
}
constexpr int WTOTAL = 425984;

__device__ uint4 g_whi4[WTOTAL / 8];   // transposed [n][k] bf16 hi, 32-k tiles
__device__ uint4 g_wlo4[WTOTAL / 8];   // lo residuals

// ---------------- smem word offsets ----------------
constexpr int O_SXH = 0;          // A hi: 64 x 20 words
constexpr int O_SXL = 1280;
constexpr int O_SWH = 2560;       // W hi: 256 x 20 words
constexpr int O_SWL = 7680;
constexpr int O_SHH = 12800;      // h hi: 64 x 132 words
constexpr int O_SHL = 21248;
constexpr int O_SB1 = 29696;
constexpr int O_SB2 = 29952;
constexpr int O_SSP = 30208;      // 64 rows x 4 wn partial sumsq
constexpr int O_PID = 30464;
constexpr int SMEM_WORDS = 30528;
constexpr int SMEM_BYTES = SMEM_WORDS * 4;   // 122,112 B (1 CTA/SM)

struct Params {
    const float* feat[3];
    const int*   pid[3];
    const float* w1[3];
    const float* b1[3];
    const float* w2[3];
    const float* b2[3];
    float*       out;
};

__device__ __forceinline__ uint32_t pack_bf2(__nv_bfloat16 lo, __nv_bfloat16 hi) {
    return (uint32_t)__bfloat16_as_ushort(hi) << 16 | (uint32_t)__bfloat16_as_ushort(lo);
}
__device__ __forceinline__ void split2(float v0, float v1, uint32_t& hw, uint32_t& lw) {
    __nv_bfloat16 h0 = __float2bfloat16(v0);
    __nv_bfloat16 h1 = __float2bfloat16(v1);
    __nv_bfloat16 l0 = __float2bfloat16(v0 - __bfloat162float(h0));
    __nv_bfloat16 l1 = __float2bfloat16(v1 - __bfloat162float(h1));
    hw = pack_bf2(h0, h1);
    lw = pack_bf2(l0, l1);
}
__device__ __forceinline__ void mma16816(float* d, const uint32_t* a,
                                         uint32_t b0, uint32_t b1) {
    asm volatile(
        "mma.sync.aligned.m16n8k16.row.col.f32.bf16.bf16.f32 "
        "{%0,%1,%2,%3}, {%4,%5,%6,%7}, {%8,%9}, {%0,%1,%2,%3};"
        : "+f"(d[0]), "+f"(d[1]), "+f"(d[2]), "+f"(d[3])
        : "r"(a[0]), "r"(a[1]), "r"(a[2]), "r"(a[3]), "r"(b0), "r"(b1));
}

// ---------------- weight prep ----------------
__global__ void prep_weights(Params P)
{
    __nv_bfloat16* ghi = (__nv_bfloat16*)g_whi4;
    __nv_bfloat16* glo = (__nv_bfloat16*)g_wlo4;
    for (int m = 0; m < 6; m++) {
        int s = m >> 1;
        bool isw2 = m & 1;
        const float* w = isw2 ? P.w2[s] : P.w1[s];
        int K   = isw2 ? 256 : (128 << s);
        int off = isw2 ? W2OFF(s) : W1OFF(s);
        int nel = K * 256;
        for (int e = blockIdx.x * blockDim.x + threadIdx.x; e < nel;
             e += gridDim.x * blockDim.x) {
            int k = e >> 8, n = e & 255;
            float v = w[e];
            __nv_bfloat16 hi = __float2bfloat16(v);
            __nv_bfloat16 lo = __float2bfloat16(v - __bfloat162float(hi));
            int d = off + (k >> 5) * 8192 + n * 32 + (k & 31);
            ghi[d] = hi;
            glo[d] = lo;
        }
    }
}

// ---------------- fused kernel: 512 thr, register-staged pipeline ----------------
__global__ void __launch_bounds__(512, 1)
fused_mma(Params P)
{
    extern __shared__ uint32_t smw[];
    uint32_t* sxh = smw + O_SXH;
    uint32_t* sxl = smw + O_SXL;
    uint32_t* swh = smw + O_SWH;
    uint32_t* swl = smw + O_SWL;
    uint32_t* shh = smw + O_SHH;
    uint32_t* shl = smw + O_SHL;
    float*    sb1 = (float*)(smw + O_SB1);
    float*    sb2 = (float*)(smw + O_SB2);
    float*    ssp = (float*)(smw + O_SSP);
    int*      spid = (int*)(smw + O_PID);

    const int tid  = threadIdx.x;
    const int lane = tid & 31;
    const int wid  = tid >> 5;
    const int wm   = wid & 3;          // rows wm*16..+15
    const int wn   = wid >> 2;         // cols wn*64..+63
    const int gr   = lane >> 2;
    const int c    = lane & 3;
    const int rowA = wm * 16 + gr;

    const int s  = blockIdx.x % 3;
    const int bi = blockIdx.x / 3;
    const int C  = 128 << s;
    const int HW = 32768 >> (2 * s);
    const int NT1 = C / KT;            // 4 / 8 / 16
    const int T   = NT1 + 8;

    const float* __restrict__ feat = P.feat[s];
    const int*   __restrict__ pid  = P.pid[s];

    const int row0 = bi * TM;
    const int b    = row0 >> 12;
    const int p0   = row0 & (PNUM - 1);

    if (tid < TM)  spid[tid] = pid[b * PNUM + p0 + tid];
    if (tid < 256) { sb1[tid] = __ldg(&P.b1[s][tid]); sb2[tid] = __ldg(&P.b2[s][tid]); }
    __syncthreads();

    const float* featb = feat + (size_t)b * C * HW;
    const __nv_bfloat16* ghi = (const __nv_bfloat16*)g_whi4;
    const __nv_bfloat16* glo = (const __nv_bfloat16*)g_wlo4;

    // gather assignment: word tid -> (row, kp), word tid+512 -> (row, kp+8)
    const int gr0 = tid & 63;          // row
    const int gkp = tid >> 6;          // 0..7
    const int mypid = spid[gr0];

    float acc[8][4];
#pragma unroll
    for (int nt = 0; nt < 8; nt++)
#pragma unroll
        for (int q = 0; q < 4; q++) acc[nt][q] = 0.f;

    uint4 pwh0, pwh1, pwl0, pwl1;      // W prefetch regs
    float va0, va1, va2, va3;          // A gather prefetch regs

    // ---- prologue: prefetch tile 0 ----
    {
        const uint4* srch = (const uint4*)(ghi + W1OFF(s));
        const uint4* srcl = (const uint4*)(glo + W1OFF(s));
        pwh0 = __ldg(&srch[tid]);  pwh1 = __ldg(&srch[tid + 512]);
        pwl0 = __ldg(&srcl[tid]);  pwl1 = __ldg(&srcl[tid + 512]);
        int k = gkp * 2;
        va0 = __ldg(&featb[(size_t)k * HW + mypid]);
        va1 = __ldg(&featb[(size_t)(k + 1) * HW + mypid]);
        int k2 = (gkp + 8) * 2;
        va2 = __ldg(&featb[(size_t)k2 * HW + mypid]);
        va3 = __ldg(&featb[(size_t)(k2 + 1) * HW + mypid]);
    }

    for (int t = 0; t < T; t++) {
        // ---- store prefetched tile into smem ----
        {
            int n0 = tid >> 2, q0 = tid & 3;
            int u1 = tid + 512;
            int n1 = u1 >> 2, q1 = u1 & 3;
            *(uint4*)((char*)swh + n0 * 80 + q0 * 16) = pwh0;
            *(uint4*)((char*)swh + n1 * 80 + q1 * 16) = pwh1;
            *(uint4*)((char*)swl + n0 * 80 + q0 * 16) = pwl0;
            *(uint4*)((char*)swl + n1 * 80 + q1 * 16) = pwl1;
        }
        if (t < NT1) {
            uint32_t hw, lw;
            split2(va0, va1, hw, lw);
            sxh[gr0 * 20 + gkp] = hw;
            sxl[gr0 * 20 + gkp] = lw;
            split2(va2, va3, hw, lw);
            sxh[gr0 * 20 + gkp + 8] = hw;
            sxl[gr0 * 20 + gkp + 8] = lw;
        }
        __syncthreads();

        // ---- prefetch tile t+1 (overlaps with MMA below) ----
        if (t + 1 < T) {
            const int woff = (t + 1 < NT1) ? (W1OFF(s) + (t + 1) * 8192)
                                           : (W2OFF(s) + (t + 1 - NT1) * 8192);
            const uint4* srch = (const uint4*)(ghi + woff);
            const uint4* srcl = (const uint4*)(glo + woff);
            pwh0 = __ldg(&srch[tid]);  pwh1 = __ldg(&srch[tid + 512]);
            pwl0 = __ldg(&srcl[tid]);  pwl1 = __ldg(&srcl[tid + 512]);
        }
        if (t + 1 < NT1) {
            int k = (t + 1) * KT + gkp * 2;
            va0 = __ldg(&featb[(size_t)k * HW + mypid]);
            va1 = __ldg(&featb[(size_t)(k + 1) * HW + mypid]);
            int k2 = (t + 1) * KT + (gkp + 8) * 2;
            va2 = __ldg(&featb[(size_t)k2 * HW + mypid]);
            va3 = __ldg(&featb[(size_t)(k2 + 1) * HW + mypid]);
        }

        // ---- MMA phase ----
        if (t < NT1) {
#pragma unroll
            for (int ks = 0; ks < 2; ks++) {
                uint32_t ah[4], al[4];
                const int ab = rowA * 20 + ks * 8 + c;
                ah[0] = sxh[ab];       ah[1] = sxh[ab + 160];
                ah[2] = sxh[ab + 4];   ah[3] = sxh[ab + 164];
                al[0] = sxl[ab];       al[1] = sxl[ab + 160];
                al[2] = sxl[ab + 4];   al[3] = sxl[ab + 164];
#pragma unroll
                for (int nt = 0; nt < 8; nt++) {
                    const int bb = (wn * 64 + nt * 8 + gr) * 20 + ks * 8 + c;
                    uint32_t bh0 = swh[bb], bh1 = swh[bb + 4];
                    uint32_t bl0 = swl[bb], bl1 = swl[bb + 4];
                    mma16816(acc[nt], ah, bh0, bh1);
                    mma16816(acc[nt], ah, bl0, bl1);
                    mma16816(acc[nt], al, bh0, bh1);
                }
            }
        } else {
            const int tt = t - NT1;
#pragma unroll
            for (int ks = 0; ks < 2; ks++) {
                uint32_t ah[4], al[4];
                const int ab = rowA * 132 + tt * 16 + ks * 8 + c;
                ah[0] = shh[ab];        ah[1] = shh[ab + 1056];
                ah[2] = shh[ab + 4];    ah[3] = shh[ab + 1060];
                al[0] = shl[ab];        al[1] = shl[ab + 1056];
                al[2] = shl[ab + 4];    al[3] = shl[ab + 1060];
#pragma unroll
                for (int nt = 0; nt < 8; nt++) {
                    const int bb = (wn * 64 + nt * 8 + gr) * 20 + ks * 8 + c;
                    uint32_t bh0 = swh[bb], bh1 = swh[bb + 4];
                    uint32_t bl0 = swl[bb], bl1 = swl[bb + 4];
                    mma16816(acc[nt], ah, bh0, bh1);
                    mma16816(acc[nt], ah, bl0, bl1);
                    mma16816(acc[nt], al, bh0, bh1);
                }
            }
        }

        // ---- GEMM1->GEMM2 boundary: h epilogue ----
        if (t == NT1 - 1) {
#pragma unroll
            for (int nt = 0; nt < 8; nt++) {
                const int n  = wn * 64 + nt * 8 + 2 * c;
                const int wi = wn * 32 + nt * 4 + c;
                float v0 = fmaxf(acc[nt][0] + sb1[n],     0.f);
                float v1 = fmaxf(acc[nt][1] + sb1[n + 1], 0.f);
                float v2 = fmaxf(acc[nt][2] + sb1[n],     0.f);
                float v3 = fmaxf(acc[nt][3] + sb1[n + 1], 0.f);
                uint32_t hw, lw;
                split2(v0, v1, hw, lw);
                shh[rowA * 132 + wi] = hw;
                shl[rowA * 132 + wi] = lw;
                split2(v2, v3, hw, lw);
                shh[(rowA + 8) * 132 + wi] = hw;
                shl[(rowA + 8) * 132 + wi] = lw;
#pragma unroll
                for (int q = 0; q < 4; q++) acc[nt][q] = 0.f;
            }
        }
        __syncthreads();
    }

    // ================= epilogue: +b2, L2 normalize, store =================
    float ss0 = 0.f, ss1 = 0.f;
#pragma unroll
    for (int nt = 0; nt < 8; nt++) {
        const int n = wn * 64 + nt * 8 + 2 * c;
        acc[nt][0] += sb2[n];
        acc[nt][1] += sb2[n + 1];
        acc[nt][2] += sb2[n];
        acc[nt][3] += sb2[n + 1];
        ss0 = fmaf(acc[nt][0], acc[nt][0], fmaf(acc[nt][1], acc[nt][1], ss0));
        ss1 = fmaf(acc[nt][2], acc[nt][2], fmaf(acc[nt][3], acc[nt][3], ss1));
    }
    ss0 += __shfl_xor_sync(0xffffffffu, ss0, 1);
    ss0 += __shfl_xor_sync(0xffffffffu, ss0, 2);
    ss1 += __shfl_xor_sync(0xffffffffu, ss1, 1);
    ss1 += __shfl_xor_sync(0xffffffffu, ss1, 2);
    if (c == 0) {
        ssp[rowA * 4 + wn]       = ss0;
        ssp[(rowA + 8) * 4 + wn] = ss1;
    }
    __syncthreads();
    const float inv0 = 1.f / (sqrtf(ssp[rowA * 4] + ssp[rowA * 4 + 1] +
                                    ssp[rowA * 4 + 2] + ssp[rowA * 4 + 3]) + 1e-7f);
    const float inv1 = 1.f / (sqrtf(ssp[(rowA + 8) * 4] + ssp[(rowA + 8) * 4 + 1] +
                                    ssp[(rowA + 8) * 4 + 2] + ssp[(rowA + 8) * 4 + 3]) + 1e-7f);

    float* __restrict__ out = P.out + ((size_t)s * ROWS + row0) * NCOL;
#pragma unroll
    for (int nt = 0; nt < 8; nt++) {
        const int n = wn * 64 + nt * 8 + 2 * c;
        float2 o0 = make_float2(acc[nt][0] * inv0, acc[nt][1] * inv0);
        float2 o1 = make_float2(acc[nt][2] * inv1, acc[nt][3] * inv1);
        *(float2*)&out[(size_t)rowA * NCOL + n]       = o0;
        *(float2*)&out[(size_t)(rowA + 8) * NCOL + n] = o1;
    }
}

// ---------------- launch ----------------
extern "C" void kernel_launch(void* const* d_in, const int* in_sizes, int n_in,
                              void* d_out, int out_size)
{
    const bool sig_order = (n_in > 1) && (in_sizes[1] == 16777216);

    Params P;
    if (sig_order) {
        for (int s = 0; s < 3; s++) {
            P.feat[s] = (const float*)d_in[s];
            P.pid[s]  = (const int*)  d_in[3 + s];
            P.w1[s]   = (const float*)d_in[6 + 4 * s];
            P.b1[s]   = (const float*)d_in[7 + 4 * s];
            P.w2[s]   = (const float*)d_in[8 + 4 * s];
            P.b2[s]   = (const float*)d_in[9 + 4 * s];
        }
    } else {
        for (int s = 0; s < 3; s++) {
            P.feat[s] = (const float*)d_in[6 * s + 0];
            P.pid[s]  = (const int*)  d_in[6 * s + 1];
            P.w1[s]   = (const float*)d_in[6 * s + 2];
            P.b1[s]   = (const float*)d_in[6 * s + 3];
            P.w2[s]   = (const float*)d_in[6 * s + 4];
            P.b2[s]   = (const float*)d_in[6 * s + 5];
        }
    }
    P.out = (float*)d_out;

    cudaFuncSetAttribute(fused_mma, cudaFuncAttributeMaxDynamicSharedMemorySize,
                         SMEM_BYTES);

    prep_weights<<<256, 256>>>(P);
    fused_mma<<<3 * (ROWS / TM), 512, SMEM_BYTES>>>(P);
}